// round 14
// baseline (speedup 1.0000x reference)
#include <cuda_runtime.h>
#include <cuda_bf16.h>
#include <stdint.h>

// x: (8, 48, 48, 48, 64) fp32.  K = reshape(x, (B, C, N)), C=64, N=110592.
#define CCH    64
#define NCOL   110592
#define BATCH  8
#define CN     (CCH * NCOL)

#define GCHUNK 768
#define NCHUNK (NCOL / GCHUNK)        // 144 partial-Gram chunks
#define GKS    32
#define GITERS (GCHUNK / GKS)         // 24

#define WTN    96
#define WBLK   (NCOL / WTN)           // 1152

// ---------------- static device scratch ------------------------------------
__device__ float         g_part[BATCH * NCHUNK * CCH * CCH];  // 18.9 MB
__device__ float         g_G[BATCH * CCH * CCH];
__device__ __nv_bfloat16 g_aff_bf[BATCH * CCH * CCH];

// ---------------- helpers ---------------------------------------------------
__device__ __forceinline__ uint32_t pk2(float lo, float hi) {
    uint32_t r;
    asm("cvt.rn.bf16x2.f32 %0, %1, %2;" : "=r"(r) : "f"(hi), "f"(lo));
    return r;
}
__device__ __forceinline__ void mma16816(float* c, const uint32_t* a, const uint32_t* b) {
    asm volatile(
        "mma.sync.aligned.m16n8k16.row.col.f32.bf16.bf16.f32 "
        "{%0,%1,%2,%3}, {%4,%5,%6,%7}, {%8,%9}, {%0,%1,%2,%3};"
        : "+f"(c[0]), "+f"(c[1]), "+f"(c[2]), "+f"(c[3])
        : "r"(a[0]), "r"(a[1]), "r"(a[2]), "r"(a[3]), "r"(b[0]), "r"(b[1]));
}
__device__ __forceinline__ void ldsm4(uint32_t* r, uint32_t a) {
    asm volatile("ldmatrix.sync.aligned.m8n8.x4.shared.b16 {%0,%1,%2,%3}, [%4];"
                 : "=r"(r[0]), "=r"(r[1]), "=r"(r[2]), "=r"(r[3]) : "r"(a));
}
__device__ __forceinline__ void ldsm4t(uint32_t* r, uint32_t a) {
    asm volatile("ldmatrix.sync.aligned.m8n8.x4.trans.shared.b16 {%0,%1,%2,%3}, [%4];"
                 : "=r"(r[0]), "=r"(r[1]), "=r"(r[2]), "=r"(r[3]) : "r"(a));
}
__device__ __forceinline__ void ldsm2t(uint32_t* r, uint32_t a) {
    asm volatile("ldmatrix.sync.aligned.m8n8.x2.trans.shared.b16 {%0,%1}, [%2];"
                 : "=r"(r[0]), "=r"(r[1]) : "r"(a));
}
__device__ __forceinline__ uint32_t smem_u32(const void* p) {
    return (uint32_t)__cvta_generic_to_shared(p);
}

// ---------------------------------------------------------------------------
// Kernel 1: partial Gram via HMMA + ldmatrix.  Block = 64 ch x 768-col chunk.
// grid (NCHUNK, BATCH), 128 threads.  Ts stride 40 bf16 -> conflict-free LDSM.
// ---------------------------------------------------------------------------
#define TSTR 40

__global__ void __launch_bounds__(128) gram_tc(const float* __restrict__ x) {
    __shared__ __align__(16) __nv_bfloat16 Ts[64 * TSTR];

    const int tid  = threadIdx.x;
    const int w    = tid >> 5;
    const int lane = tid & 31;
    const int gid  = lane >> 2;
    const int tig  = lane & 3;
    const int b    = blockIdx.y;
    const long n0  = (long)blockIdx.x * GCHUNK;

    const int lr = tid >> 1, lh = tid & 1;
    const float* src = x + (long)b * CN + (long)lr * NCOL + n0 + lh * 16;

    const uint32_t ts0 = smem_u32(Ts);
    // A ldsm addr (per kk add 32B): row = w*16 + (l&7) + ((l>>3)&1)*8, col = (l>>4)*8
    const uint32_t aAddr = ts0 +
        (uint32_t)((w * 16 + (lane & 7) + ((lane >> 3) & 1) * 8) * TSTR +
                   ((lane >> 4) * 8)) * 2;
    // B ldsm addr (p = nt pair; per kk add 32B): row = 16p + ((l>>4)&1)*8 + (l&7),
    // col = ((l>>3)&1)*8
    const uint32_t bAddr0 = ts0 +
        (uint32_t)((((lane >> 4) & 1) * 8 + (lane & 7)) * TSTR +
                   (((lane >> 3) & 1) * 8)) * 2;

    float4 pf[4];
#pragma unroll
    for (int j = 0; j < 4; j++) pf[j] = *(const float4*)(src + j * 4);

    float acc[8][4] = {};

    for (int it = 0; it < GITERS; it++) {
        __syncthreads();
        {
            uint4 s0 = make_uint4(pk2(pf[0].x, pf[0].y), pk2(pf[0].z, pf[0].w),
                                  pk2(pf[1].x, pf[1].y), pk2(pf[1].z, pf[1].w));
            uint4 s1 = make_uint4(pk2(pf[2].x, pf[2].y), pk2(pf[2].z, pf[2].w),
                                  pk2(pf[3].x, pf[3].y), pk2(pf[3].z, pf[3].w));
            __nv_bfloat16* d = &Ts[lr * TSTR + lh * 16];
            *(uint4*)(d)     = s0;
            *(uint4*)(d + 8) = s1;
        }
        if (it + 1 < GITERS) {
            const float* s = src + (it + 1) * GKS;
#pragma unroll
            for (int j = 0; j < 4; j++) pf[j] = *(const float4*)(s + j * 4);
        }
        __syncthreads();

#pragma unroll
        for (int kk = 0; kk < 2; kk++) {
            uint32_t a[4];
            ldsm4(a, aAddr + kk * 32);
            uint32_t br[16];
#pragma unroll
            for (int p = 0; p < 4; p++)
                ldsm4(br + p * 4, bAddr0 + (uint32_t)(p * 16 * TSTR * 2) + kk * 32);
#pragma unroll
            for (int p = 0; p < 4; p++) {
                mma16816(acc[2 * p],     a, br + p * 4);
                mma16816(acc[2 * p + 1], a, br + p * 4 + 2);
            }
        }
    }

    float* op = g_part + ((long)b * NCHUNK + blockIdx.x) * (CCH * CCH);
#pragma unroll
    for (int nt = 0; nt < 8; nt++) {
        const int c0  = w * 16 + gid;
        const int col = nt * 8 + tig * 2;
        *(float2*)&op[c0 * CCH + col]       = make_float2(acc[nt][0], acc[nt][1]);
        *(float2*)&op[(c0 + 8) * CCH + col] = make_float2(acc[nt][2], acc[nt][3]);
    }
}

// ---------------------------------------------------------------------------
// Kernel 2a: reduce partials -> G.  grid (16, BATCH), 256 threads.
// ---------------------------------------------------------------------------
__global__ void reduce_g() {
    const int b    = blockIdx.y;
    const int elem = blockIdx.x * 256 + threadIdx.x;
    const float* p = g_part + (long)b * NCHUNK * (CCH * CCH) + elem;

    float s0 = 0.f, s1 = 0.f, s2 = 0.f, s3 = 0.f;
#pragma unroll 1
    for (int ch = 0; ch < NCHUNK; ch += 4) {
        s0 += p[(long)(ch + 0) * (CCH * CCH)];
        s1 += p[(long)(ch + 1) * (CCH * CCH)];
        s2 += p[(long)(ch + 2) * (CCH * CCH)];
        s3 += p[(long)(ch + 3) * (CCH * CCH)];
    }
    g_G[b * (CCH * CCH) + elem] = (s0 + s1) + (s2 + s3);
}

// ---------------------------------------------------------------------------
// Kernel 2b: m3 = G@G (symmetric), sigmoid -> bf16.  grid (BATCH).
// ---------------------------------------------------------------------------
__global__ void m3_sigmoid() {
    __shared__ float Gs[CCH * CCH];
    const int b   = blockIdx.x;
    const int tid = threadIdx.x;              // 256

    const float4* src = (const float4*)(g_G + b * (CCH * CCH));
    for (int i = tid; i < (CCH * CCH) / 4; i += 256)
        ((float4*)Gs)[i] = src[i];
    __syncthreads();

    const int c  = tid >> 2;
    const int e0 = (tid & 3) * 16;
    for (int e = e0; e < e0 + 16; e++) {
        float s = 0.0f;
#pragma unroll
        for (int d = 0; d < CCH; d++)
            s = fmaf(Gs[c * CCH + d], Gs[e * CCH + d], s);
        g_aff_bf[b * (CCH * CCH) + c * CCH + e] =
            __float2bfloat16(1.0f / (1.0f + __expf(-s)));
    }
}

// ---------------------------------------------------------------------------
// Kernel 3: out = x + gamma * (A @ K) via HMMA + ldmatrix.  M=64, N=96, K=64.
// x converted straight to bf16 Ks[d][n] at load (no fp32 SMEM copy); the
// residual is re-read in the epilogue via LDG — those lines are L1-resident.
// 256 threads / 8 warps: wm = w>>2 -> m-rows wm*32..+31; wn = w&3 -> n-cols
// wn*24..+23.  grid (WBLK, BATCH).  smem 22.5 KB.
// ---------------------------------------------------------------------------
#define ASTR 72
#define KSTR 104

__global__ void __launch_bounds__(256) weights_tc(const float* __restrict__ x,
                                                  const float* __restrict__ gamma_p,
                                                  float* __restrict__ out) {
    __shared__ __align__(16) __nv_bfloat16 As[64 * ASTR];   //  9216 B
    __shared__ __align__(16) __nv_bfloat16 Ks[64 * KSTR];   // 13312 B

    const int tid  = threadIdx.x;
    const int w    = tid >> 5;
    const int lane = tid & 31;
    const int gid  = lane >> 2;
    const int tig  = lane & 3;
    const int wm   = w >> 2;
    const int wn   = w & 3;
    const int b    = blockIdx.y;
    const long n0  = (long)blockIdx.x * WTN;

    // load x tile fp32 (4 threads/row, 24 floats each) -> bf16 Ks only
    {
        const int r = tid >> 2, q = tid & 3;
        const float* s = x + (long)b * CN + (long)r * NCOL + n0 + q * 24;
        float4 v[6];
#pragma unroll
        for (int i = 0; i < 6; i++) v[i] = *(const float4*)(s + i * 4);
        __nv_bfloat16* dk = &Ks[r * KSTR + q * 24];
#pragma unroll
        for (int i = 0; i < 3; i++) {
            *(uint4*)(dk + i * 8) = make_uint4(
                pk2(v[2 * i].x, v[2 * i].y),   pk2(v[2 * i].z, v[2 * i].w),
                pk2(v[2 * i + 1].x, v[2 * i + 1].y), pk2(v[2 * i + 1].z, v[2 * i + 1].w));
        }
    }
    // load affinity bf16 -> As[64][64] (stride 72)
    {
        const int r = tid >> 2, h = tid & 3;
        const uint4* s = (const uint4*)(g_aff_bf + b * (CCH * CCH) + r * CCH + h * 16);
        *(uint4*)&As[r * ASTR + h * 16]     = s[0];
        *(uint4*)&As[r * ASTR + h * 16 + 8] = s[1];
    }
    __syncthreads();

    const uint32_t as0 = smem_u32(As);
    const uint32_t ks0 = smem_u32(Ks);
    // A ldsm (non-trans) addr for mi: row = (wm*2+mi)*16 + (l&7) + ((l>>3)&1)*8,
    // col = (l>>4)*8 ; per kt add 32B.
    uint32_t aAddr[2];
#pragma unroll
    for (int mi = 0; mi < 2; mi++)
        aAddr[mi] = as0 + (uint32_t)((((wm * 2 + mi) * 16 + (lane & 7) +
                    ((lane >> 3) & 1) * 8) * ASTR + (lane >> 4) * 8)) * 2;
    // B ldsm.trans x4 (nt 0,1): krow = ((l>>3)&1)*8 + (l&7),
    // ncol = wn*24 + ((l>>4)&1)*8 ; per kt add 16*KSTR*2.
    const uint32_t b4Addr = ks0 + (uint32_t)(((((lane >> 3) & 1) * 8 + (lane & 7)) * KSTR
                          + wn * 24 + ((lane >> 4) & 1) * 8)) * 2;
    // B ldsm.trans x2 (nt 2): lanes 0-15 supply addrs; ncol = wn*24 + 16.
    const uint32_t b2Addr = ks0 + (uint32_t)(((((lane >> 3) & 1) * 8 + (lane & 7)) * KSTR
                          + wn * 24 + 16)) * 2;

    float acc[2][3][4] = {};

#pragma unroll
    for (int kt = 0; kt < 4; kt++) {
        uint32_t a0[4], a1[4], b01[4], b2[2];
        ldsm4 (a0,  aAddr[0] + kt * 32);
        ldsm4 (a1,  aAddr[1] + kt * 32);
        ldsm4t(b01, b4Addr + kt * (16 * KSTR * 2));
        ldsm2t(b2,  b2Addr + kt * (16 * KSTR * 2));
        mma16816(acc[0][0], a0, b01);
        mma16816(acc[0][1], a0, b01 + 2);
        mma16816(acc[0][2], a0, b2);
        mma16816(acc[1][0], a1, b01);
        mma16816(acc[1][1], a1, b01 + 2);
        mma16816(acc[1][2], a1, b2);
    }

    const float g = *gamma_p;

#pragma unroll
    for (int mi = 0; mi < 2; mi++) {
#pragma unroll
        for (int nt = 0; nt < 3; nt++) {
            const int c0 = (wm * 2 + mi) * 16 + gid;
            const int n  = wn * 24 + nt * 8 + tig * 2;
            const long off0 = (long)b * CN + (long)c0 * NCOL + n0 + n;
            const long off1 = off0 + 8l * NCOL;
            float2 x0 = *(const float2*)(x + off0);    // L1-resident (loaded above)
            float2 x1 = *(const float2*)(x + off1);
            *(float2*)(out + off0) = make_float2(fmaf(g, acc[mi][nt][0], x0.x),
                                                 fmaf(g, acc[mi][nt][1], x0.y));
            *(float2*)(out + off1) = make_float2(fmaf(g, acc[mi][nt][2], x1.x),
                                                 fmaf(g, acc[mi][nt][3], x1.y));
        }
    }
}

// ---------------------------------------------------------------------------
extern "C" void kernel_launch(void* const* d_in, const int* in_sizes, int n_in,
                              void* d_out, int out_size) {
    const float* x     = (const float*)d_in[0];
    const float* gamma = (const float*)d_in[1];
    float*       out   = (float*)d_out;

    gram_tc    <<<dim3(NCHUNK, BATCH), 128>>>(x);
    reduce_g   <<<dim3(16, BATCH), 256>>>();
    m3_sigmoid <<<BATCH, 256>>>();
    weights_tc <<<dim3(WBLK, BATCH), 256>>>(x, gamma, out);
}

// round 15
// speedup vs baseline: 1.1013x; 1.1013x over previous
#include <cuda_runtime.h>
#include <cuda_bf16.h>
#include <stdint.h>

// x: (8, 48, 48, 48, 64) fp32.  K = reshape(x, (B, C, N)), C=64, N=110592.
#define CCH    64
#define NCOL   110592
#define BATCH  8
#define CN     (CCH * NCOL)

#define GCHUNK 1024
#define NCHUNK (NCOL / GCHUNK)        // 108 partial-Gram chunks
#define GKS    32
#define GITERS (GCHUNK / GKS)         // 32

#define WTN    96
#define WBLK   (NCOL / WTN)           // 1152

// ---------------- static device scratch ------------------------------------
__device__ float         g_part[BATCH * NCHUNK * CCH * CCH];  // 14.2 MB
__device__ float         g_G[BATCH * CCH * CCH];
__device__ __nv_bfloat16 g_aff_bf[BATCH * CCH * CCH];

// ---------------- helpers ---------------------------------------------------
__device__ __forceinline__ uint32_t pk2(float lo, float hi) {
    uint32_t r;
    asm("cvt.rn.bf16x2.f32 %0, %1, %2;" : "=r"(r) : "f"(hi), "f"(lo));
    return r;
}
__device__ __forceinline__ void mma16816(float* c, const uint32_t* a, const uint32_t* b) {
    asm volatile(
        "mma.sync.aligned.m16n8k16.row.col.f32.bf16.bf16.f32 "
        "{%0,%1,%2,%3}, {%4,%5,%6,%7}, {%8,%9}, {%0,%1,%2,%3};"
        : "+f"(c[0]), "+f"(c[1]), "+f"(c[2]), "+f"(c[3])
        : "r"(a[0]), "r"(a[1]), "r"(a[2]), "r"(a[3]), "r"(b[0]), "r"(b[1]));
}
__device__ __forceinline__ void ldsm4(uint32_t* r, uint32_t a) {
    asm volatile("ldmatrix.sync.aligned.m8n8.x4.shared.b16 {%0,%1,%2,%3}, [%4];"
                 : "=r"(r[0]), "=r"(r[1]), "=r"(r[2]), "=r"(r[3]) : "r"(a));
}
__device__ __forceinline__ void ldsm4t(uint32_t* r, uint32_t a) {
    asm volatile("ldmatrix.sync.aligned.m8n8.x4.trans.shared.b16 {%0,%1,%2,%3}, [%4];"
                 : "=r"(r[0]), "=r"(r[1]), "=r"(r[2]), "=r"(r[3]) : "r"(a));
}
__device__ __forceinline__ void ldsm2t(uint32_t* r, uint32_t a) {
    asm volatile("ldmatrix.sync.aligned.m8n8.x2.trans.shared.b16 {%0,%1}, [%2];"
                 : "=r"(r[0]), "=r"(r[1]) : "r"(a));
}
__device__ __forceinline__ uint32_t smem_u32(const void* p) {
    return (uint32_t)__cvta_generic_to_shared(p);
}

// ---------------------------------------------------------------------------
// Kernel 1: partial Gram via HMMA + ldmatrix.  Block = 64 ch x 1024-col chunk.
// grid (NCHUNK, BATCH), 128 threads.  Ts stride 40 bf16 -> conflict-free LDSM.
// ---------------------------------------------------------------------------
#define TSTR 40

__global__ void __launch_bounds__(128) gram_tc(const float* __restrict__ x) {
    __shared__ __align__(16) __nv_bfloat16 Ts[64 * TSTR];

    const int tid  = threadIdx.x;
    const int w    = tid >> 5;
    const int lane = tid & 31;
    const int gid  = lane >> 2;
    const int tig  = lane & 3;
    const int b    = blockIdx.y;
    const long n0  = (long)blockIdx.x * GCHUNK;

    const int lr = tid >> 1, lh = tid & 1;
    const float* src = x + (long)b * CN + (long)lr * NCOL + n0 + lh * 16;

    const uint32_t ts0 = smem_u32(Ts);
    // A ldsm addr (per kk add 32B): row = w*16 + (l&7) + ((l>>3)&1)*8, col = (l>>4)*8
    const uint32_t aAddr = ts0 +
        (uint32_t)((w * 16 + (lane & 7) + ((lane >> 3) & 1) * 8) * TSTR +
                   ((lane >> 4) * 8)) * 2;
    // B ldsm addr (p = nt pair; per kk add 32B): row = 16p + ((l>>4)&1)*8 + (l&7),
    // col = ((l>>3)&1)*8
    const uint32_t bAddr0 = ts0 +
        (uint32_t)((((lane >> 4) & 1) * 8 + (lane & 7)) * TSTR +
                   (((lane >> 3) & 1) * 8)) * 2;

    float4 pf[4];
#pragma unroll
    for (int j = 0; j < 4; j++) pf[j] = *(const float4*)(src + j * 4);

    float acc[8][4] = {};

    for (int it = 0; it < GITERS; it++) {
        __syncthreads();
        {
            uint4 s0 = make_uint4(pk2(pf[0].x, pf[0].y), pk2(pf[0].z, pf[0].w),
                                  pk2(pf[1].x, pf[1].y), pk2(pf[1].z, pf[1].w));
            uint4 s1 = make_uint4(pk2(pf[2].x, pf[2].y), pk2(pf[2].z, pf[2].w),
                                  pk2(pf[3].x, pf[3].y), pk2(pf[3].z, pf[3].w));
            __nv_bfloat16* d = &Ts[lr * TSTR + lh * 16];
            *(uint4*)(d)     = s0;
            *(uint4*)(d + 8) = s1;
        }
        if (it + 1 < GITERS) {
            const float* s = src + (it + 1) * GKS;
#pragma unroll
            for (int j = 0; j < 4; j++) pf[j] = *(const float4*)(s + j * 4);
        }
        __syncthreads();

#pragma unroll
        for (int kk = 0; kk < 2; kk++) {
            uint32_t a[4];
            ldsm4(a, aAddr + kk * 32);
            uint32_t br[16];
#pragma unroll
            for (int p = 0; p < 4; p++)
                ldsm4(br + p * 4, bAddr0 + (uint32_t)(p * 16 * TSTR * 2) + kk * 32);
#pragma unroll
            for (int p = 0; p < 4; p++) {
                mma16816(acc[2 * p],     a, br + p * 4);
                mma16816(acc[2 * p + 1], a, br + p * 4 + 2);
            }
        }
    }

    float* op = g_part + ((long)b * NCHUNK + blockIdx.x) * (CCH * CCH);
#pragma unroll
    for (int nt = 0; nt < 8; nt++) {
        const int c0  = w * 16 + gid;
        const int col = nt * 8 + tig * 2;
        *(float2*)&op[c0 * CCH + col]       = make_float2(acc[nt][0], acc[nt][1]);
        *(float2*)&op[(c0 + 8) * CCH + col] = make_float2(acc[nt][2], acc[nt][3]);
    }
}

// ---------------------------------------------------------------------------
// Kernel 2a: reduce partials -> G.  grid (16, BATCH), 256 threads.
// ---------------------------------------------------------------------------
__global__ void reduce_g() {
    const int b    = blockIdx.y;
    const int elem = blockIdx.x * 256 + threadIdx.x;
    const float* p = g_part + (long)b * NCHUNK * (CCH * CCH) + elem;

    float s0 = 0.f, s1 = 0.f, s2 = 0.f, s3 = 0.f;
#pragma unroll 1
    for (int ch = 0; ch < NCHUNK; ch += 4) {
        s0 += p[(long)(ch + 0) * (CCH * CCH)];
        s1 += p[(long)(ch + 1) * (CCH * CCH)];
        s2 += p[(long)(ch + 2) * (CCH * CCH)];
        s3 += p[(long)(ch + 3) * (CCH * CCH)];
    }
    g_G[b * (CCH * CCH) + elem] = (s0 + s1) + (s2 + s3);
}

// ---------------------------------------------------------------------------
// Kernel 2b: m3 = G@G (symmetric), sigmoid -> bf16.  grid (BATCH).
// ---------------------------------------------------------------------------
__global__ void m3_sigmoid() {
    __shared__ float Gs[CCH * CCH];
    const int b   = blockIdx.x;
    const int tid = threadIdx.x;              // 256

    const float4* src = (const float4*)(g_G + b * (CCH * CCH));
    for (int i = tid; i < (CCH * CCH) / 4; i += 256)
        ((float4*)Gs)[i] = src[i];
    __syncthreads();

    const int c  = tid >> 2;
    const int e0 = (tid & 3) * 16;
    for (int e = e0; e < e0 + 16; e++) {
        float s = 0.0f;
#pragma unroll
        for (int d = 0; d < CCH; d++)
            s = fmaf(Gs[c * CCH + d], Gs[e * CCH + d], s);
        g_aff_bf[b * (CCH * CCH) + c * CCH + e] =
            __float2bfloat16(1.0f / (1.0f + __expf(-s)));
    }
}

// ---------------------------------------------------------------------------
// Kernel 3: out = x + gamma * (A @ K) via HMMA + ldmatrix.  M=64, N=96, K=64.
// The loader thread keeps its 24 residual floats in registers; after the mma
// the scaled result is staged through SMEM (Ds) so the final store happens in
// the LOAD mapping: 6 fully-coalesced STG.128 per thread.  No fp32 x copy.
// 256 threads / 8 warps: wm = w>>2 -> m-rows wm*32..+31; wn = w&3 -> n-cols
// wn*24..+23.  grid (WBLK, BATCH).  smem 48.1 KB.
// ---------------------------------------------------------------------------
#define ASTR 72
#define KSTR 104
#define DSTR 100

__global__ void __launch_bounds__(256) weights_tc(const float* __restrict__ x,
                                                  const float* __restrict__ gamma_p,
                                                  float* __restrict__ out) {
    __shared__ __align__(16) __nv_bfloat16 As[64 * ASTR];   //  9216 B
    __shared__ __align__(16) __nv_bfloat16 Ks[64 * KSTR];   // 13312 B
    __shared__ __align__(16) float         Ds[64 * DSTR];   // 25600 B

    const int tid  = threadIdx.x;
    const int w    = tid >> 5;
    const int lane = tid & 31;
    const int gid  = lane >> 2;
    const int tig  = lane & 3;
    const int wm   = w >> 2;
    const int wn   = w & 3;
    const int b    = blockIdx.y;
    const long n0  = (long)blockIdx.x * WTN;

    const int r = tid >> 2, q = tid & 3;      // loader/epilogue mapping

    // load x tile fp32 (4 threads/row, 24 floats each); keep v for residual
    float4 v[6];
    {
        const float* s = x + (long)b * CN + (long)r * NCOL + n0 + q * 24;
#pragma unroll
        for (int i = 0; i < 6; i++) v[i] = *(const float4*)(s + i * 4);
        __nv_bfloat16* dk = &Ks[r * KSTR + q * 24];
#pragma unroll
        for (int i = 0; i < 3; i++) {
            *(uint4*)(dk + i * 8) = make_uint4(
                pk2(v[2 * i].x, v[2 * i].y),   pk2(v[2 * i].z, v[2 * i].w),
                pk2(v[2 * i + 1].x, v[2 * i + 1].y), pk2(v[2 * i + 1].z, v[2 * i + 1].w));
        }
    }
    // load affinity bf16 -> As[64][64] (stride 72)
    {
        const uint4* s = (const uint4*)(g_aff_bf + b * (CCH * CCH) + r * CCH + q * 16);
        *(uint4*)&As[r * ASTR + q * 16]     = s[0];
        *(uint4*)&As[r * ASTR + q * 16 + 8] = s[1];
    }
    __syncthreads();

    const uint32_t as0 = smem_u32(As);
    const uint32_t ks0 = smem_u32(Ks);
    // A ldsm (non-trans) addr for mi: row = (wm*2+mi)*16 + (l&7) + ((l>>3)&1)*8,
    // col = (l>>4)*8 ; per kt add 32B.
    uint32_t aAddr[2];
#pragma unroll
    for (int mi = 0; mi < 2; mi++)
        aAddr[mi] = as0 + (uint32_t)((((wm * 2 + mi) * 16 + (lane & 7) +
                    ((lane >> 3) & 1) * 8) * ASTR + (lane >> 4) * 8)) * 2;
    // B ldsm.trans x4 (nt 0,1): krow = ((l>>3)&1)*8 + (l&7),
    // ncol = wn*24 + ((l>>4)&1)*8 ; per kt add 16*KSTR*2.
    const uint32_t b4Addr = ks0 + (uint32_t)(((((lane >> 3) & 1) * 8 + (lane & 7)) * KSTR
                          + wn * 24 + ((lane >> 4) & 1) * 8)) * 2;
    // B ldsm.trans x2 (nt 2): lanes 0-15 supply addrs; ncol = wn*24 + 16.
    const uint32_t b2Addr = ks0 + (uint32_t)(((((lane >> 3) & 1) * 8 + (lane & 7)) * KSTR
                          + wn * 24 + 16)) * 2;

    float acc[2][3][4] = {};

#pragma unroll
    for (int kt = 0; kt < 4; kt++) {
        uint32_t a0[4], a1[4], b01[4], b2[2];
        ldsm4 (a0,  aAddr[0] + kt * 32);
        ldsm4 (a1,  aAddr[1] + kt * 32);
        ldsm4t(b01, b4Addr + kt * (16 * KSTR * 2));
        ldsm2t(b2,  b2Addr + kt * (16 * KSTR * 2));
        mma16816(acc[0][0], a0, b01);
        mma16816(acc[0][1], a0, b01 + 2);
        mma16816(acc[0][2], a0, b2);
        mma16816(acc[1][0], a1, b01);
        mma16816(acc[1][1], a1, b01 + 2);
        mma16816(acc[1][2], a1, b2);
    }

    const float g = *gamma_p;

    // stage gamma*acc into Ds[c][n] (SMEM scatter is cheap; <=2-way conflicts)
#pragma unroll
    for (int mi = 0; mi < 2; mi++) {
#pragma unroll
        for (int nt = 0; nt < 3; nt++) {
            const int c0 = (wm * 2 + mi) * 16 + gid;
            const int n  = wn * 24 + nt * 8 + tig * 2;
            *(float2*)&Ds[c0 * DSTR + n] =
                make_float2(g * acc[mi][nt][0], g * acc[mi][nt][1]);
            *(float2*)&Ds[(c0 + 8) * DSTR + n] =
                make_float2(g * acc[mi][nt][2], g * acc[mi][nt][3]);
        }
    }
    __syncthreads();

    // epilogue in the LOAD mapping: out[r][q*24..+23] = v + Ds  (coalesced STG.128)
    {
        float* dst = out + (long)b * CN + (long)r * NCOL + n0 + q * 24;
        const float* ds = &Ds[r * DSTR + q * 24];
#pragma unroll
        for (int i = 0; i < 6; i++) {
            float4 d4 = *(const float4*)(ds + i * 4);
            *(float4*)(dst + i * 4) = make_float4(v[i].x + d4.x, v[i].y + d4.y,
                                                  v[i].z + d4.z, v[i].w + d4.w);
        }
    }
}

// ---------------------------------------------------------------------------
extern "C" void kernel_launch(void* const* d_in, const int* in_sizes, int n_in,
                              void* d_out, int out_size) {
    const float* x     = (const float*)d_in[0];
    const float* gamma = (const float*)d_in[1];
    float*       out   = (float*)d_out;

    gram_tc    <<<dim3(NCHUNK, BATCH), 128>>>(x);
    reduce_g   <<<dim3(16, BATCH), 256>>>();
    m3_sigmoid <<<BATCH, 256>>>();
    weights_tc <<<dim3(WBLK, BATCH), 256>>>(x, gamma, out);
}